// round 1
// baseline (speedup 1.0000x reference)
#include <cuda_runtime.h>
#include <math.h>

#define Bq 4
#define Nq 4096
#define Hq 8
#define Dq 64
#define Mq 64

// Scratch: KV accumulators [b][h][d][m] and K row-sums [b][h][d]
__device__ float g_KV[Bq*Hq*Dq*Mq];
__device__ float g_Ksum[Bq*Hq*Dq];

__device__ __forceinline__ float fmap(float x) {
    // elu(x) + 1
    return x > 0.0f ? x + 1.0f : expf(x);
}

__global__ void zero_kernel() {
    int i = blockIdx.x * blockDim.x + threadIdx.x;
    if (i < Bq*Hq*Dq*Mq) g_KV[i] = 0.0f;
    if (i < Bq*Hq*Dq)    g_Ksum[i] = 0.0f;
}

// pass1: KV[b,h,d,m] += fmap(K[b,n,h,d]) * V[b,n,h,m]; Ksum[b,h,d] += fmap(K)
// grid (16, H, B), block 256. Each block handles 256 rows (4 chunks of 64).
__global__ void __launch_bounds__(256) pass1_kernel(const float* __restrict__ Kp,
                                                    const float* __restrict__ Vp) {
    __shared__ float Ksh[64][64];
    __shared__ float Vsh[64][64];

    const int b = blockIdx.z, h = blockIdx.y;
    const int tid = threadIdx.x;
    const int d0 = (tid & 15) * 4;   // 4 d-values per thread
    const int m0 = (tid >> 4) * 4;   // 4 m-values per thread

    float acc[4][4];
    #pragma unroll
    for (int i = 0; i < 4; i++)
        #pragma unroll
        for (int j = 0; j < 4; j++) acc[i][j] = 0.0f;
    float ks0 = 0.f, ks1 = 0.f, ks2 = 0.f, ks3 = 0.f;

    for (int c = 0; c < 4; c++) {
        const int n0 = blockIdx.x * 256 + c * 64;
        __syncthreads();
        // stage 64 rows of K (feature-mapped) and V
        #pragma unroll
        for (int i = tid; i < 64 * 16; i += 256) {
            const int row = i >> 4;
            const int c4  = i & 15;
            const int n   = n0 + row;
            const size_t base = ((size_t)(b * Nq + n) * Hq + h);
            float4 k4 = *(const float4*)(Kp + base * Dq + c4 * 4);
            k4.x = fmap(k4.x); k4.y = fmap(k4.y);
            k4.z = fmap(k4.z); k4.w = fmap(k4.w);
            *(float4*)&Ksh[row][c4 * 4] = k4;
            *(float4*)&Vsh[row][c4 * 4] =
                *(const float4*)(Vp + base * Mq + c4 * 4);
        }
        __syncthreads();

        #pragma unroll 4
        for (int n = 0; n < 64; n++) {
            float4 k4 = *(const float4*)&Ksh[n][d0];
            float4 v4 = *(const float4*)&Vsh[n][m0];
            float kk[4] = {k4.x, k4.y, k4.z, k4.w};
            float vv[4] = {v4.x, v4.y, v4.z, v4.w};
            #pragma unroll
            for (int mi = 0; mi < 4; mi++)
                #pragma unroll
                for (int di = 0; di < 4; di++)
                    acc[mi][di] += vv[mi] * kk[di];
            if (m0 == 0) { ks0 += kk[0]; ks1 += kk[1]; ks2 += kk[2]; ks3 += kk[3]; }
        }
    }

    // flush to global accumulators
    float* kv = g_KV + (size_t)(b * Hq + h) * Dq * Mq;
    #pragma unroll
    for (int di = 0; di < 4; di++)
        #pragma unroll
        for (int mi = 0; mi < 4; mi++)
            atomicAdd(&kv[(d0 + di) * Mq + (m0 + mi)], acc[mi][di]);

    if (m0 == 0) {
        float* kss = g_Ksum + (b * Hq + h) * Dq + d0;
        atomicAdd(&kss[0], ks0);
        atomicAdd(&kss[1], ks1);
        atomicAdd(&kss[2], ks2);
        atomicAdd(&kss[3], ks3);
    }
}

// pass2: out[b,n,h,m] = Z(b,n,h) * sum_d fmap(Q[b,n,h,d]) * KV[b,h,d,m]
// grid (64, H, B), block 256. Each block handles 64 rows of n.
__global__ void __launch_bounds__(256) pass2_kernel(const float* __restrict__ Qp,
                                                    float* __restrict__ Op) {
    __shared__ float KVsh[Dq][Mq];   // [d][m]
    __shared__ float Qsh[64][68];    // [n][d], padded stride 68 (conflict-free)
    __shared__ float Zsh[64];
    __shared__ float Kss[64];

    const int b = blockIdx.z, h = blockIdx.y;
    const int n0 = blockIdx.x * 64;
    const int tid = threadIdx.x;

    // load KV tile (16 KB, linear)
    const float4* kvg = (const float4*)(g_KV + (size_t)(b * Hq + h) * Dq * Mq);
    #pragma unroll
    for (int i = tid; i < Dq * Mq / 4; i += 256)
        ((float4*)KVsh)[i] = kvg[i];

    if (tid < 64) Kss[tid] = g_Ksum[(b * Hq + h) * Dq + tid];

    // load Q rows (feature-mapped)
    #pragma unroll
    for (int i = tid; i < 64 * 16; i += 256) {
        const int row = i >> 4;
        const int c4  = i & 15;
        const int n   = n0 + row;
        float4 q4 = *(const float4*)(Qp + ((size_t)(b * Nq + n) * Hq + h) * Dq + c4 * 4);
        q4.x = fmap(q4.x); q4.y = fmap(q4.y);
        q4.z = fmap(q4.z); q4.w = fmap(q4.w);
        *(float4*)&Qsh[row][c4 * 4] = q4;
    }
    __syncthreads();

    // per-row normalizer Z = 1 / (Q . Ksum + eps)
    if (tid < 64) {
        float s = 0.0f;
        #pragma unroll
        for (int d = 0; d < Dq; d++) s += Qsh[tid][d] * Kss[d];
        Zsh[tid] = 1.0f / (s + 1e-6f);
    }
    __syncthreads();

    const int m0 = (tid & 15) * 4;
    const int nb = (tid >> 4) * 4;
    float acc[4][4];
    #pragma unroll
    for (int i = 0; i < 4; i++)
        #pragma unroll
        for (int j = 0; j < 4; j++) acc[i][j] = 0.0f;

    #pragma unroll 4
    for (int d = 0; d < Dq; d++) {
        float4 kv4 = *(const float4*)&KVsh[d][m0];
        float kvr[4] = {kv4.x, kv4.y, kv4.z, kv4.w};
        float qr[4] = {Qsh[nb][d], Qsh[nb + 1][d], Qsh[nb + 2][d], Qsh[nb + 3][d]};
        #pragma unroll
        for (int ni = 0; ni < 4; ni++)
            #pragma unroll
            for (int mi = 0; mi < 4; mi++)
                acc[ni][mi] += qr[ni] * kvr[mi];
    }

    #pragma unroll
    for (int ni = 0; ni < 4; ni++) {
        const float z = Zsh[nb + ni];
        float4 o;
        o.x = acc[ni][0] * z; o.y = acc[ni][1] * z;
        o.z = acc[ni][2] * z; o.w = acc[ni][3] * z;
        *(float4*)(Op + ((size_t)(b * Nq + n0 + nb + ni) * Hq + h) * Mq + m0) = o;
    }
}

extern "C" void kernel_launch(void* const* d_in, const int* in_sizes, int n_in,
                              void* d_out, int out_size) {
    const float* Q = (const float*)d_in[0];
    const float* K = (const float*)d_in[1];
    const float* V = (const float*)d_in[2];
    float* out = (float*)d_out;

    zero_kernel<<<512, 256>>>();
    pass1_kernel<<<dim3(16, Hq, Bq), 256>>>(K, V);
    pass2_kernel<<<dim3(64, Hq, Bq), 256>>>(Q, out);
}

// round 2
// speedup vs baseline: 1.0229x; 1.0229x over previous
#include <cuda_runtime.h>
#include <math.h>

#define Bq 4
#define Nq 4096
#define Hq 8
#define Dq 64
#define Mq 64

typedef unsigned long long u64;

// Scratch: KV accumulators [b][h][d][m] and K row-sums [b][h][d]
__device__ float g_KV[Bq*Hq*Dq*Mq];
__device__ float g_Ksum[Bq*Hq*Dq];

__device__ __forceinline__ float fmap(float x) {
    // elu(x) + 1
    return x > 0.0f ? x + 1.0f : __expf(x);
}

// ---- packed f32x2 helpers (sm_103a FFMA2 path) ----
__device__ __forceinline__ u64 pack_dup(float v) {
    u64 r; asm("mov.b64 %0, {%1, %1};" : "=l"(r) : "f"(v)); return r;
}
__device__ __forceinline__ void ffma2(u64 &acc, u64 a, u64 b) {
    asm("fma.rn.f32x2 %0, %1, %2, %0;" : "+l"(acc) : "l"(a), "l"(b));
}
__device__ __forceinline__ void fadd2(u64 &acc, u64 a) {
    asm("add.rn.f32x2 %0, %1, %0;" : "+l"(acc) : "l"(a));
}
__device__ __forceinline__ float2 unpack2(u64 v) {
    float2 f; asm("mov.b64 {%0, %1}, %2;" : "=f"(f.x), "=f"(f.y) : "l"(v)); return f;
}

__global__ void zero_kernel() {
    int i = blockIdx.x * blockDim.x + threadIdx.x;
    if (i < Bq*Hq*Dq*Mq) g_KV[i] = 0.0f;
    if (i < Bq*Hq*Dq)    g_Ksum[i] = 0.0f;
}

// pass1: KV[b,h,d,m] += fmap(K[b,n,h,d]) * V[b,n,h,m]; Ksum[b,h,d] += fmap(K)
// grid (16, H, B), block 256. Each block handles 256 rows (4 chunks of 64).
__global__ void __launch_bounds__(256) pass1_kernel(const float* __restrict__ Kp,
                                                    const float* __restrict__ Vp) {
    __shared__ float Ksh[64][64];
    __shared__ float Vsh[64][64];

    const int b = blockIdx.z, h = blockIdx.y;
    const int tid = threadIdx.x;
    const int d0 = (tid & 15) * 4;   // 4 d-values per thread (2 packed pairs)
    const int m0 = (tid >> 4) * 4;   // 4 m-values per thread

    u64 acc2[4][2];                  // [mi][d-pair]
    #pragma unroll
    for (int i = 0; i < 4; i++) { acc2[i][0] = 0ull; acc2[i][1] = 0ull; }
    u64 ks2[2] = {0ull, 0ull};

    for (int c = 0; c < 4; c++) {
        const int n0 = blockIdx.x * 256 + c * 64;
        __syncthreads();
        // stage 64 rows of K (feature-mapped) and V
        #pragma unroll
        for (int i = tid; i < 64 * 16; i += 256) {
            const int row = i >> 4;
            const int c4  = i & 15;
            const int n   = n0 + row;
            const size_t base = ((size_t)(b * Nq + n) * Hq + h);
            float4 k4 = *(const float4*)(Kp + base * Dq + c4 * 4);
            k4.x = fmap(k4.x); k4.y = fmap(k4.y);
            k4.z = fmap(k4.z); k4.w = fmap(k4.w);
            *(float4*)&Ksh[row][c4 * 4] = k4;
            *(float4*)&Vsh[row][c4 * 4] =
                *(const float4*)(Vp + base * Mq + c4 * 4);
        }
        __syncthreads();

        #pragma unroll 4
        for (int n = 0; n < 64; n++) {
            // kk pairs come free from the 128-bit shared load
            const ulonglong2 kk = *(const ulonglong2*)&Ksh[n][d0];
            const float4 v4 = *(const float4*)&Vsh[n][m0];
            const u64 vb0 = pack_dup(v4.x);
            const u64 vb1 = pack_dup(v4.y);
            const u64 vb2 = pack_dup(v4.z);
            const u64 vb3 = pack_dup(v4.w);
            ffma2(acc2[0][0], vb0, kk.x); ffma2(acc2[0][1], vb0, kk.y);
            ffma2(acc2[1][0], vb1, kk.x); ffma2(acc2[1][1], vb1, kk.y);
            ffma2(acc2[2][0], vb2, kk.x); ffma2(acc2[2][1], vb2, kk.y);
            ffma2(acc2[3][0], vb3, kk.x); ffma2(acc2[3][1], vb3, kk.y);
            if (m0 == 0) { fadd2(ks2[0], kk.x); fadd2(ks2[1], kk.y); }
        }
    }

    // flush to global accumulators
    float* kv = g_KV + (size_t)(b * Hq + h) * Dq * Mq;
    #pragma unroll
    for (int mi = 0; mi < 4; mi++) {
        float2 p0 = unpack2(acc2[mi][0]);
        float2 p1 = unpack2(acc2[mi][1]);
        atomicAdd(&kv[(d0 + 0) * Mq + (m0 + mi)], p0.x);
        atomicAdd(&kv[(d0 + 1) * Mq + (m0 + mi)], p0.y);
        atomicAdd(&kv[(d0 + 2) * Mq + (m0 + mi)], p1.x);
        atomicAdd(&kv[(d0 + 3) * Mq + (m0 + mi)], p1.y);
    }

    if (m0 == 0) {
        float* kss = g_Ksum + (b * Hq + h) * Dq + d0;
        float2 s0 = unpack2(ks2[0]);
        float2 s1 = unpack2(ks2[1]);
        atomicAdd(&kss[0], s0.x);
        atomicAdd(&kss[1], s0.y);
        atomicAdd(&kss[2], s1.x);
        atomicAdd(&kss[3], s1.y);
    }
}

// pass2: out[b,n,h,m] = Z(b,n,h) * sum_d fmap(Q[b,n,h,d]) * KV[b,h,d,m]
// grid (64, H, B), block 256. Each block handles 64 rows of n.
__global__ void __launch_bounds__(256) pass2_kernel(const float* __restrict__ Qp,
                                                    float* __restrict__ Op) {
    __shared__ float KVsh[Dq][Mq];   // [d][m]
    __shared__ float Qsh[64][68];    // [n][d], padded stride 68 (conflict-free)
    __shared__ float Zsh[64];
    __shared__ float Kss[64];

    const int b = blockIdx.z, h = blockIdx.y;
    const int n0 = blockIdx.x * 64;
    const int tid = threadIdx.x;

    // load KV tile (16 KB, linear)
    const float4* kvg = (const float4*)(g_KV + (size_t)(b * Hq + h) * Dq * Mq);
    #pragma unroll
    for (int i = tid; i < Dq * Mq / 4; i += 256)
        ((float4*)KVsh)[i] = kvg[i];

    if (tid < 64) Kss[tid] = g_Ksum[(b * Hq + h) * Dq + tid];

    // load Q rows (feature-mapped)
    #pragma unroll
    for (int i = tid; i < 64 * 16; i += 256) {
        const int row = i >> 4;
        const int c4  = i & 15;
        const int n   = n0 + row;
        float4 q4 = *(const float4*)(Qp + ((size_t)(b * Nq + n) * Hq + h) * Dq + c4 * 4);
        q4.x = fmap(q4.x); q4.y = fmap(q4.y);
        q4.z = fmap(q4.z); q4.w = fmap(q4.w);
        *(float4*)&Qsh[row][c4 * 4] = q4;
    }
    __syncthreads();

    // per-row normalizer Z = 1 / (Q . Ksum + eps)
    if (tid < 64) {
        float s = 0.0f;
        #pragma unroll
        for (int d = 0; d < Dq; d++) s += Qsh[tid][d] * Kss[d];
        Zsh[tid] = 1.0f / (s + 1e-6f);
    }
    __syncthreads();

    const int m0 = (tid & 15) * 4;   // 4 m-values (2 packed pairs)
    const int nb = (tid >> 4) * 4;   // 4 n-rows
    u64 acc2[4][2];                  // [ni][m-pair]
    #pragma unroll
    for (int i = 0; i < 4; i++) { acc2[i][0] = 0ull; acc2[i][1] = 0ull; }

    #pragma unroll 4
    for (int d = 0; d < Dq; d++) {
        const ulonglong2 kv2 = *(const ulonglong2*)&KVsh[d][m0];
        const u64 q0 = pack_dup(Qsh[nb + 0][d]);
        const u64 q1 = pack_dup(Qsh[nb + 1][d]);
        const u64 q2 = pack_dup(Qsh[nb + 2][d]);
        const u64 q3 = pack_dup(Qsh[nb + 3][d]);
        ffma2(acc2[0][0], q0, kv2.x); ffma2(acc2[0][1], q0, kv2.y);
        ffma2(acc2[1][0], q1, kv2.x); ffma2(acc2[1][1], q1, kv2.y);
        ffma2(acc2[2][0], q2, kv2.x); ffma2(acc2[2][1], q2, kv2.y);
        ffma2(acc2[3][0], q3, kv2.x); ffma2(acc2[3][1], q3, kv2.y);
    }

    #pragma unroll
    for (int ni = 0; ni < 4; ni++) {
        const float z = Zsh[nb + ni];
        float2 p0 = unpack2(acc2[ni][0]);
        float2 p1 = unpack2(acc2[ni][1]);
        float4 o;
        o.x = p0.x * z; o.y = p0.y * z;
        o.z = p1.x * z; o.w = p1.y * z;
        *(float4*)(Op + ((size_t)(b * Nq + n0 + nb + ni) * Hq + h) * Mq + m0) = o;
    }
}

extern "C" void kernel_launch(void* const* d_in, const int* in_sizes, int n_in,
                              void* d_out, int out_size) {
    const float* Q = (const float*)d_in[0];
    const float* K = (const float*)d_in[1];
    const float* V = (const float*)d_in[2];
    float* out = (float*)d_out;

    zero_kernel<<<512, 256>>>();
    pass1_kernel<<<dim3(16, Hq, Bq), 256>>>(K, V);
    pass2_kernel<<<dim3(64, Hq, Bq), 256>>>(Q, out);
}